// round 1
// baseline (speedup 1.0000x reference)
#include <cuda_runtime.h>
#include <math.h>

#define N_ENT 50000
#define N_REL 237
#define N_TYPE 4000
#define DE 100
#define NOUT 128
#define DT 200
#define N_EDGE 800000
#define BATCH 4096
#define NUM_FILT 32
#define CONV_W 60
#define POOL_W 30
#define FC_LEN 960
#define EPS 1e-5f

// ---------------- scratch (static device allocations) ----------------
__device__ float g_h[N_ENT * NOUT];        // node features after W_f
__device__ float g_hd[N_ENT];              // h . a[:128]
__device__ float g_hm[N_ENT];              // h . a[128:]
__device__ float g_rproj[N_REL * NOUT];    // R_w @ W_f
__device__ float g_ra[N_REL];              // rproj . a[128:]
__device__ float g_denom[N_ENT];
__device__ float g_ex[N_EDGE];
__device__ float g_agg[N_ENT * NOUT];
__device__ float g_e[BATCH * NOUT];
__device__ float g_conv[BATCH * NUM_FILT * CONV_W];
__device__ float g_y[BATCH * DT];
__device__ float g_fcT[FC_LEN * DT];
__device__ float g_bn1[4];                              // sum, sumsq, scale, shift
__device__ float g_bn3sum[NUM_FILT], g_bn3ss[NUM_FILT];
__device__ float g_bn3sc[NUM_FILT], g_bn3sh[NUM_FILT];
__device__ float g_bn2sum[DT], g_bn2ss[DT];
__device__ float g_bn2sc[DT], g_bn2sh[DT];

// ---------------- kernels ----------------

__global__ void k_zero() {
    int tid = blockIdx.x * blockDim.x + threadIdx.x;
    int stride = gridDim.x * blockDim.x;
    for (int i = tid; i < N_ENT * NOUT; i += stride) g_agg[i] = 0.f;
    for (int i = tid; i < N_ENT; i += stride) g_denom[i] = 0.f;
    if (tid < 2) g_bn1[tid] = 0.f;
    for (int i = tid; i < NUM_FILT; i += stride) { g_bn3sum[i] = 0.f; g_bn3ss[i] = 0.f; }
    for (int i = tid; i < DT; i += stride) { g_bn2sum[i] = 0.f; g_bn2ss[i] = 0.f; }
}

// rproj = R_w @ W_f ; ra = rproj . a2    (grid N_REL, block NOUT)
__global__ void k_rproj(const float* __restrict__ Rw, const float* __restrict__ Wf,
                        const float* __restrict__ av) {
    int r = blockIdx.x, j = threadIdx.x;
    __shared__ float rr[DE];
    __shared__ float red[NOUT];
    if (j < DE) rr[j] = Rw[r * DE + j];
    __syncthreads();
    float acc = 0.f;
#pragma unroll 4
    for (int k = 0; k < DE; k++) acc += rr[k] * Wf[k * NOUT + j];
    g_rproj[r * NOUT + j] = acc;
    red[j] = acc * av[NOUT + j];
    __syncthreads();
    for (int s = 64; s > 0; s >>= 1) {
        if (j < s) red[j] += red[j + s];
        __syncthreads();
    }
    if (j == 0) g_ra[r] = red[0];
}

// h = E_w @ W_f ; hd = h.a1 ; hm = h.a2   (grid N_ENT, block NOUT)
__global__ void k_h(const float* __restrict__ Ew, const float* __restrict__ Wf,
                    const float* __restrict__ av) {
    int n = blockIdx.x, j = threadIdx.x;
    __shared__ float er[DE];
    __shared__ float r1[NOUT], r2[NOUT];
    if (j < DE) er[j] = Ew[n * DE + j];
    __syncthreads();
    float acc = 0.f;
#pragma unroll 4
    for (int k = 0; k < DE; k++) acc += er[k] * Wf[k * NOUT + j];
    g_h[n * NOUT + j] = acc;
    r1[j] = acc * av[j];
    r2[j] = acc * av[NOUT + j];
    __syncthreads();
    for (int s = 64; s > 0; s >>= 1) {
        if (j < s) { r1[j] += r1[j + s]; r2[j] += r2[j + s]; }
        __syncthreads();
    }
    if (j == 0) { g_hd[n] = r1[0]; g_hm[n] = r2[0]; }
}

// per-edge: score -> leaky_relu -> exp ; accumulate denom[dst]
__global__ void k_score(const int* __restrict__ ei, const int* __restrict__ et) {
    int e = blockIdx.x * blockDim.x + threadIdx.x;
    if (e >= N_EDGE) return;
    int src = ei[e], dst = ei[N_EDGE + e], t = et[e];
    float s = g_hd[dst] + g_hm[src] - g_ra[t];
    s = (s >= 0.f) ? s : 0.2f * s;
    float ex = expf(s);
    g_ex[e] = ex;
    atomicAdd(&g_denom[dst], ex);
}

// per-edge scatter: agg[dst] += att * (h[src] - rproj[type]); warp per edge
__global__ void k_agg(const int* __restrict__ ei, const int* __restrict__ et) {
    long long gt = (long long)blockIdx.x * blockDim.x + threadIdx.x;
    int e = (int)(gt >> 5);
    int lane = threadIdx.x & 31;
    if (e >= N_EDGE) return;
    int src = ei[e], dst = ei[N_EDGE + e], t = et[e];
    float w = g_ex[e] / (g_denom[dst] + 1e-16f);
    float4 a = reinterpret_cast<const float4*>(&g_h[src * NOUT])[lane];
    float4 b = reinterpret_cast<const float4*>(&g_rproj[t * NOUT])[lane];
    float4 v;
    v.x = w * (a.x - b.x); v.y = w * (a.y - b.y);
    v.z = w * (a.z - b.z); v.w = w * (a.w - b.w);
    float* p = &g_agg[dst * NOUT + lane * 4];
    asm volatile("red.global.add.v4.f32 [%0], {%1,%2,%3,%4};"
                 :: "l"(p), "f"(v.x), "f"(v.y), "f"(v.z), "f"(v.w) : "memory");
}

// gather batch rows, elu, accumulate global bn1 stats  (grid BATCH, block NOUT)
__global__ void k_gather(const int* __restrict__ xb) {
    int b = blockIdx.x, j = threadIdx.x;
    __shared__ float r1[NOUT], r2[NOUT];
    float v = g_agg[xb[b] * NOUT + j];
    float e = (v > 0.f) ? v : expm1f(v);
    g_e[b * NOUT + j] = e;
    r1[j] = e;
    r2[j] = e * e;
    __syncthreads();
    for (int s = 64; s > 0; s >>= 1) {
        if (j < s) { r1[j] += r1[j + s]; r2[j] += r2[j + s]; }
        __syncthreads();
    }
    if (j == 0) { atomicAdd(&g_bn1[0], r1[0]); atomicAdd(&g_bn1[1], r2[0]); }
}

__global__ void k_bn1fin(const float* __restrict__ g, const float* __restrict__ b) {
    float cnt = (float)(BATCH * NOUT);
    float mean = g_bn1[0] / cnt;
    float var = g_bn1[1] / cnt - mean * mean;
    float inv = rsqrtf(var + EPS);
    float sc = g[0] * inv;
    g_bn1[2] = sc;
    g_bn1[3] = b[0] - sc * mean;
}

// conv (bn1 folded into input), + conv_b ; accumulate per-channel bn3 stats
__global__ void k_conv(const float* __restrict__ cw, const float* __restrict__ cb) {
    int b = blockIdx.x, tid = threadIdx.x;
    __shared__ float es[NOUT];
    __shared__ float wsm[NUM_FILT * 9];
    __shared__ float co[NUM_FILT * CONV_W];
    float sc = g_bn1[2], sh = g_bn1[3];
    if (tid < NOUT) es[tid] = sc * g_e[b * NOUT + tid] + sh;
    for (int i = tid; i < NUM_FILT * 9; i += blockDim.x) wsm[i] = cw[i];
    __syncthreads();
    for (int i = tid; i < NUM_FILT * CONV_W; i += blockDim.x) {
        int c = i / CONV_W, w = i % CONV_W;
        float acc = cb[c];
#pragma unroll
        for (int k = 0; k < 9; k++) acc += wsm[c * 9 + k] * es[2 * w + k];
        co[i] = acc;
        g_conv[b * NUM_FILT * CONV_W + i] = acc;
    }
    __syncthreads();
    if (tid < NUM_FILT) {
        float s = 0.f, ss = 0.f;
        for (int w = 0; w < CONV_W; w++) {
            float v = co[tid * CONV_W + w];
            s += v; ss += v * v;
        }
        atomicAdd(&g_bn3sum[tid], s);
        atomicAdd(&g_bn3ss[tid], ss);
    }
}

__global__ void k_bn3fin(const float* __restrict__ g, const float* __restrict__ b) {
    int c = threadIdx.x;
    if (c >= NUM_FILT) return;
    float cnt = (float)(BATCH * CONV_W);
    float mean = g_bn3sum[c] / cnt;
    float var = g_bn3ss[c] / cnt - mean * mean;
    float inv = rsqrtf(var + EPS);
    float sc = g[c] * inv;
    g_bn3sc[c] = sc;
    g_bn3sh[c] = b[c] - sc * mean;
}

// transpose fc_w [DT, FC_LEN] -> g_fcT [FC_LEN, DT]
__global__ void k_fct(const float* __restrict__ fcw) {
    int i = blockIdx.x * blockDim.x + threadIdx.x;
    if (i < FC_LEN * DT) {
        int k = i / FC_LEN, f = i % FC_LEN;
        g_fcT[f * DT + k] = fcw[i];
    }
}

// bn3 + relu + maxpool + fc ; accumulate bn2 per-feature stats. 8 batch rows/block.
__global__ void k_fc(const float* __restrict__ fcb) {
    int b0 = blockIdx.x * 8, tid = threadIdx.x;
    __shared__ float fs[8 * FC_LEN];
    for (int i = tid; i < 8 * FC_LEN; i += blockDim.x) {
        int bl = i / FC_LEN, f = i % FC_LEN;
        int c = f / POOL_W, w = f % POOL_W;
        const float* cp = &g_conv[(b0 + bl) * NUM_FILT * CONV_W + c * CONV_W + 2 * w];
        float sc = g_bn3sc[c], sh = g_bn3sh[c];
        float v = fmaxf(sc * cp[0] + sh, sc * cp[1] + sh);
        fs[i] = fmaxf(v, 0.f);   // relu(max) == max(relu) (relu monotone)
    }
    __syncthreads();
    if (tid < DT) {
        int k = tid;
        float bias = fcb[k];
        float acc[8];
#pragma unroll
        for (int l = 0; l < 8; l++) acc[l] = bias;
        for (int i = 0; i < FC_LEN; i++) {
            float wv = g_fcT[i * DT + k];
#pragma unroll
            for (int l = 0; l < 8; l++) acc[l] += fs[l * FC_LEN + i] * wv;
        }
        float s = 0.f, ss = 0.f;
#pragma unroll
        for (int l = 0; l < 8; l++) {
            g_y[(b0 + l) * DT + k] = acc[l];
            s += acc[l];
            ss += acc[l] * acc[l];
        }
        atomicAdd(&g_bn2sum[k], s);
        atomicAdd(&g_bn2ss[k], ss);
    }
}

__global__ void k_bn2fin(const float* __restrict__ g, const float* __restrict__ b) {
    int k = threadIdx.x;
    if (k >= DT) return;
    float cnt = (float)BATCH;
    float mean = g_bn2sum[k] / cnt;
    float var = g_bn2ss[k] / cnt - mean * mean;
    float inv = rsqrtf(var + EPS);
    float sc = g[k] * inv;
    g_bn2sc[k] = sc;
    g_bn2sh[k] = b[k] - sc * mean;
}

// final: z = relu(bn2(y)); out = sigmoid(z @ T_w^T + b_bias)
// tiled GEMM: 64x64 tile, 16x16 threads, 4x4 microtile, BK=16
#define GBM 64
#define GBN 64
#define GBK 16
__global__ void k_out(const float* __restrict__ Tw, const float* __restrict__ bbias,
                      float* __restrict__ out) {
    __shared__ float As[GBK][GBM];
    __shared__ float Bs[GBK][GBN];
    int tx = threadIdx.x, ty = threadIdx.y;
    int tid = ty * 16 + tx;
    int bm = blockIdx.x * GBM, bn = blockIdx.y * GBN;
    float acc[4][4];
#pragma unroll
    for (int i = 0; i < 4; i++)
#pragma unroll
        for (int j = 0; j < 4; j++) acc[i][j] = 0.f;

    int row = tid >> 2;          // 0..63
    int k0 = (tid & 3) * 4;      // 0,4,8,12

    for (int kt = 0; kt < DT; kt += GBK) {
#pragma unroll
        for (int q = 0; q < 4; q++) {
            int k = kt + k0 + q;
            float va = 0.f;
            if (k < DT)
                va = fmaxf(g_bn2sc[k] * g_y[(bm + row) * DT + k] + g_bn2sh[k], 0.f);
            As[k0 + q][row] = va;
            float vb = 0.f;
            if (k < DT && bn + row < N_TYPE) vb = Tw[(bn + row) * DT + k];
            Bs[k0 + q][row] = vb;
        }
        __syncthreads();
#pragma unroll
        for (int kk = 0; kk < GBK; kk++) {
            float a[4], bv[4];
#pragma unroll
            for (int i = 0; i < 4; i++) a[i] = As[kk][ty * 4 + i];
#pragma unroll
            for (int j = 0; j < 4; j++) bv[j] = Bs[kk][tx * 4 + j];
#pragma unroll
            for (int i = 0; i < 4; i++)
#pragma unroll
                for (int j = 0; j < 4; j++) acc[i][j] += a[i] * bv[j];
        }
        __syncthreads();
    }
#pragma unroll
    for (int i = 0; i < 4; i++) {
        int m = bm + ty * 4 + i;
#pragma unroll
        for (int j = 0; j < 4; j++) {
            int n = bn + tx * 4 + j;
            if (n < N_TYPE) {
                float l = acc[i][j] + bbias[n];
                out[m * N_TYPE + n] = 1.f / (1.f + expf(-l));
            }
        }
    }
}

// ---------------- launch ----------------
extern "C" void kernel_launch(void* const* d_in, const int* in_sizes, int n_in,
                              void* d_out, int out_size) {
    const int* xb = (const int*)d_in[0];
    const int* ei = (const int*)d_in[1];
    const int* et = (const int*)d_in[2];
    const float* Ew = (const float*)d_in[3];
    const float* Rw = (const float*)d_in[4];
    const float* Tw = (const float*)d_in[5];
    const float* Wf = (const float*)d_in[6];
    const float* av = (const float*)d_in[7];
    const float* cw = (const float*)d_in[8];
    const float* cb = (const float*)d_in[9];
    const float* b1g = (const float*)d_in[10];
    const float* b1b = (const float*)d_in[11];
    const float* b3g = (const float*)d_in[12];
    const float* b3b = (const float*)d_in[13];
    const float* b2g = (const float*)d_in[14];
    const float* b2b = (const float*)d_in[15];
    const float* fcw = (const float*)d_in[16];
    const float* fcb = (const float*)d_in[17];
    const float* bbias = (const float*)d_in[18];
    float* out = (float*)d_out;

    k_zero<<<1024, 256>>>();
    k_rproj<<<N_REL, NOUT>>>(Rw, Wf, av);
    k_h<<<N_ENT, NOUT>>>(Ew, Wf, av);
    k_score<<<(N_EDGE + 255) / 256, 256>>>(ei, et);
    {
        long long total = (long long)N_EDGE * 32;
        int blocks = (int)((total + 255) / 256);
        k_agg<<<blocks, 256>>>(ei, et);
    }
    k_gather<<<BATCH, NOUT>>>(xb);
    k_bn1fin<<<1, 1>>>(b1g, b1b);
    k_conv<<<BATCH, 256>>>(cw, cb);
    k_bn3fin<<<1, 32>>>(b3g, b3b);
    k_fct<<<(FC_LEN * DT + 255) / 256, 256>>>(fcw);
    k_fc<<<BATCH / 8, 256>>>(fcb);
    k_bn2fin<<<1, DT>>>(b2g, b2b);
    dim3 gg(BATCH / GBM, (N_TYPE + GBN - 1) / GBN);
    dim3 bb(16, 16);
    k_out<<<gg, bb>>>(Tw, bbias, out);
}

// round 2
// speedup vs baseline: 1.1677x; 1.1677x over previous
#include <cuda_runtime.h>
#include <math.h>

#define N_ENT 50000
#define N_REL 237
#define N_TYPE 4000
#define DE 100
#define NOUT 128
#define DT 200
#define DTP 208
#define N_EDGE 800000
#define BATCH 4096
#define NUM_FILT 32
#define CONV_W 60
#define POOL_W 30
#define FC_LEN 960
#define EPS 1e-5f

// ---------------- scratch ----------------
__device__ float g_h[N_ENT * NOUT];
__device__ float g_hd[N_ENT];
__device__ float g_hm[N_ENT];
__device__ float g_wa1[DE];
__device__ float g_wa2[DE];
__device__ float g_rproj[N_REL * NOUT];
__device__ float g_ra[N_REL];
__device__ float g_denom[N_ENT];
__device__ int   g_flag[N_ENT];
__device__ int   g_ecnt;
__device__ int   g_cs[N_EDGE];
__device__ int   g_cd[N_EDGE];
__device__ int   g_ct[N_EDGE];
__device__ float g_ex[N_EDGE];
__device__ float g_agg[N_ENT * NOUT];
__device__ float g_e[BATCH * NOUT];
__device__ float g_conv[BATCH * NUM_FILT * CONV_W];
__device__ float g_y[BATCH * DT];
__device__ float g_z[BATCH * DTP];          // relu(bn2), zero-padded K
__device__ float g_bn1[4];
__device__ float g_bn3sum[NUM_FILT], g_bn3ss[NUM_FILT];
__device__ float g_bn3sc[NUM_FILT], g_bn3sh[NUM_FILT];
__device__ float g_bn2sum[DT], g_bn2ss[DT];
__device__ float g_bn2sc[DT], g_bn2sh[DT];

// ---------------- kernels ----------------

__global__ void k_zero() {
    int tid = blockIdx.x * blockDim.x + threadIdx.x;
    int stride = gridDim.x * blockDim.x;
    for (int i = tid; i < N_ENT; i += stride) { g_denom[i] = 0.f; g_flag[i] = 0; }
    if (tid == 0) g_ecnt = 0;
    if (tid < 2) g_bn1[tid] = 0.f;
    for (int i = tid; i < NUM_FILT; i += stride) { g_bn3sum[i] = 0.f; g_bn3ss[i] = 0.f; }
    for (int i = tid; i < DT; i += stride) { g_bn2sum[i] = 0.f; g_bn2ss[i] = 0.f; }
}

// flag needed dst nodes + zero exactly their agg rows. grid BATCH, block NOUT
__global__ void k_flag(const int* __restrict__ xb) {
    int n = xb[blockIdx.x];
    if (threadIdx.x == 0) g_flag[n] = 1;
    g_agg[n * NOUT + threadIdx.x] = 0.f;
}

// compact edges whose dst is flagged
__global__ void k_compact(const int* __restrict__ ei, const int* __restrict__ et) {
    int e = blockIdx.x * blockDim.x + threadIdx.x;
    if (e >= N_EDGE) return;
    int dst = ei[N_EDGE + e];
    if (g_flag[dst]) {
        int pos = atomicAdd(&g_ecnt, 1);
        g_cs[pos] = ei[e];
        g_cd[pos] = dst;
        g_ct[pos] = et[e];
    }
}

// wa1 = W_f @ a1, wa2 = W_f @ a2   (1 block, 128 threads)
__global__ void k_wa(const float* __restrict__ Wf, const float* __restrict__ av) {
    int k = threadIdx.x;
    if (k >= DE) return;
    float s1 = 0.f, s2 = 0.f;
#pragma unroll 8
    for (int j = 0; j < NOUT; j++) {
        float w = Wf[k * NOUT + j];
        s1 += w * av[j];
        s2 += w * av[NOUT + j];
    }
    g_wa1[k] = s1;
    g_wa2[k] = s2;
}

// hd[n] = Ew[n].wa1, hm[n] = Ew[n].wa2   (warp per node)
__global__ void k_hd(const float* __restrict__ Ew) {
    int n = blockIdx.x * (blockDim.x / 32) + (threadIdx.x >> 5);
    int lane = threadIdx.x & 31;
    if (n >= N_ENT) return;
    const float* row = Ew + n * DE;
    float s1 = 0.f, s2 = 0.f;
    for (int k = lane; k < DE; k += 32) {
        float v = row[k];
        s1 += v * g_wa1[k];
        s2 += v * g_wa2[k];
    }
#pragma unroll
    for (int o = 16; o > 0; o >>= 1) {
        s1 += __shfl_xor_sync(0xffffffffu, s1, o);
        s2 += __shfl_xor_sync(0xffffffffu, s2, o);
    }
    if (lane == 0) { g_hd[n] = s1; g_hm[n] = s2; }
}

// h = Ew @ Wf : 16 nodes per block, 128 threads, each thread 4 nodes x 4 j
__global__ void k_h16(const float* __restrict__ Ew, const float* __restrict__ Wf) {
    int n0 = blockIdx.x * 16;
    int t = threadIdx.x;
    int jl = t & 31;
    int ng = t >> 5;  // 0..3
    __shared__ float er[16][DE];
    for (int i = t; i < 16 * DE; i += 128) er[i / DE][i % DE] = Ew[n0 * DE + i];
    __syncthreads();
    float acc[4][4];
#pragma unroll
    for (int a = 0; a < 4; a++)
#pragma unroll
        for (int b = 0; b < 4; b++) acc[a][b] = 0.f;
    for (int k = 0; k < DE; k++) {
        float w0 = Wf[k * NOUT + jl];
        float w1 = Wf[k * NOUT + jl + 32];
        float w2 = Wf[k * NOUT + jl + 64];
        float w3 = Wf[k * NOUT + jl + 96];
#pragma unroll
        for (int nn = 0; nn < 4; nn++) {
            float e = er[ng * 4 + nn][k];
            acc[nn][0] += e * w0;
            acc[nn][1] += e * w1;
            acc[nn][2] += e * w2;
            acc[nn][3] += e * w3;
        }
    }
#pragma unroll
    for (int nn = 0; nn < 4; nn++)
#pragma unroll
        for (int q = 0; q < 4; q++)
            g_h[(n0 + ng * 4 + nn) * NOUT + q * 32 + jl] = acc[nn][q];
}

// rproj = R_w @ W_f ; ra = rproj . a2    (grid N_REL, block NOUT)
__global__ void k_rproj(const float* __restrict__ Rw, const float* __restrict__ Wf,
                        const float* __restrict__ av) {
    int r = blockIdx.x, j = threadIdx.x;
    __shared__ float rr[DE];
    __shared__ float red[NOUT];
    if (j < DE) rr[j] = Rw[r * DE + j];
    __syncthreads();
    float acc = 0.f;
#pragma unroll 4
    for (int k = 0; k < DE; k++) acc += rr[k] * Wf[k * NOUT + j];
    g_rproj[r * NOUT + j] = acc;
    red[j] = acc * av[NOUT + j];
    __syncthreads();
    for (int s = 64; s > 0; s >>= 1) {
        if (j < s) red[j] += red[j + s];
        __syncthreads();
    }
    if (j == 0) g_ra[r] = red[0];
}

// per-compacted-edge: score -> leaky_relu -> exp ; accumulate denom[dst]
__global__ void k_score() {
    int tid = blockIdx.x * blockDim.x + threadIdx.x;
    int stride = gridDim.x * blockDim.x;
    int cnt = g_ecnt;
    for (int e = tid; e < cnt; e += stride) {
        int src = g_cs[e], dst = g_cd[e], t = g_ct[e];
        float s = g_hd[dst] + g_hm[src] - g_ra[t];
        s = (s >= 0.f) ? s : 0.2f * s;
        float ex = expf(s);
        g_ex[e] = ex;
        atomicAdd(&g_denom[dst], ex);
    }
}

// warp-per-compacted-edge scatter: agg[dst] += att * (h[src] - rproj[type])
__global__ void k_agg() {
    int w = (blockIdx.x * blockDim.x + threadIdx.x) >> 5;
    int nwarp = (gridDim.x * blockDim.x) >> 5;
    int lane = threadIdx.x & 31;
    int cnt = g_ecnt;
    for (int e = w; e < cnt; e += nwarp) {
        int src = g_cs[e], dst = g_cd[e], t = g_ct[e];
        float wt = g_ex[e] / (g_denom[dst] + 1e-16f);
        float4 a = reinterpret_cast<const float4*>(&g_h[src * NOUT])[lane];
        float4 b = reinterpret_cast<const float4*>(&g_rproj[t * NOUT])[lane];
        float4 v;
        v.x = wt * (a.x - b.x); v.y = wt * (a.y - b.y);
        v.z = wt * (a.z - b.z); v.w = wt * (a.w - b.w);
        float* p = &g_agg[dst * NOUT + lane * 4];
        asm volatile("red.global.add.v4.f32 [%0], {%1,%2,%3,%4};"
                     :: "l"(p), "f"(v.x), "f"(v.y), "f"(v.z), "f"(v.w) : "memory");
    }
}

// gather batch rows, elu, accumulate global bn1 stats
__global__ void k_gather(const int* __restrict__ xb) {
    int b = blockIdx.x, j = threadIdx.x;
    __shared__ float r1[NOUT], r2[NOUT];
    float v = g_agg[xb[b] * NOUT + j];
    float e = (v > 0.f) ? v : expm1f(v);
    g_e[b * NOUT + j] = e;
    r1[j] = e;
    r2[j] = e * e;
    __syncthreads();
    for (int s = 64; s > 0; s >>= 1) {
        if (j < s) { r1[j] += r1[j + s]; r2[j] += r2[j + s]; }
        __syncthreads();
    }
    if (j == 0) { atomicAdd(&g_bn1[0], r1[0]); atomicAdd(&g_bn1[1], r2[0]); }
}

__global__ void k_bn1fin(const float* __restrict__ g, const float* __restrict__ b) {
    float cnt = (float)(BATCH * NOUT);
    float mean = g_bn1[0] / cnt;
    float var = g_bn1[1] / cnt - mean * mean;
    float inv = rsqrtf(var + EPS);
    float sc = g[0] * inv;
    g_bn1[2] = sc;
    g_bn1[3] = b[0] - sc * mean;
}

// conv (bn1 folded into input) + conv_b ; per-channel bn3 stats
__global__ void k_conv(const float* __restrict__ cw, const float* __restrict__ cb) {
    int b = blockIdx.x, tid = threadIdx.x;
    __shared__ float es[NOUT];
    __shared__ float wsm[NUM_FILT * 9];
    __shared__ float co[NUM_FILT * CONV_W];
    float sc = g_bn1[2], sh = g_bn1[3];
    if (tid < NOUT) es[tid] = sc * g_e[b * NOUT + tid] + sh;
    for (int i = tid; i < NUM_FILT * 9; i += blockDim.x) wsm[i] = cw[i];
    __syncthreads();
    for (int i = tid; i < NUM_FILT * CONV_W; i += blockDim.x) {
        int c = i / CONV_W, w = i % CONV_W;
        float acc = cb[c];
#pragma unroll
        for (int k = 0; k < 9; k++) acc += wsm[c * 9 + k] * es[2 * w + k];
        co[i] = acc;
        g_conv[b * NUM_FILT * CONV_W + i] = acc;
    }
    __syncthreads();
    if (tid < NUM_FILT) {
        float s = 0.f, ss = 0.f;
        for (int w = 0; w < CONV_W; w++) {
            float v = co[tid * CONV_W + w];
            s += v; ss += v * v;
        }
        atomicAdd(&g_bn3sum[tid], s);
        atomicAdd(&g_bn3ss[tid], ss);
    }
}

__global__ void k_bn3fin(const float* __restrict__ g, const float* __restrict__ b) {
    int c = threadIdx.x;
    if (c >= NUM_FILT) return;
    float cnt = (float)(BATCH * CONV_W);
    float mean = g_bn3sum[c] / cnt;
    float var = g_bn3ss[c] / cnt - mean * mean;
    float inv = rsqrtf(var + EPS);
    float sc = g[c] * inv;
    g_bn3sc[c] = sc;
    g_bn3sh[c] = b[c] - sc * mean;
}

// bn3 + relu + maxpool + fc ; bn2 stats. 8 batch rows/block, float4 inner loop.
#define FCB 8
__global__ void k_fc(const float* __restrict__ fcw, const float* __restrict__ fcb) {
    int b0 = blockIdx.x * FCB, tid = threadIdx.x;
    __shared__ float fs[FCB * FC_LEN];  // 30 KB
    for (int i = tid; i < FCB * FC_LEN; i += blockDim.x) {
        int bl = i / FC_LEN, f = i % FC_LEN;
        int c = f / POOL_W, w = f % POOL_W;
        const float* cp = &g_conv[(b0 + bl) * NUM_FILT * CONV_W + c * CONV_W + 2 * w];
        float sc = g_bn3sc[c], sh = g_bn3sh[c];
        float v = fmaxf(sc * cp[0] + sh, sc * cp[1] + sh);
        fs[i] = fmaxf(v, 0.f);
    }
    __syncthreads();
    if (tid < DT) {
        float bias = fcb[tid];
        float acc[FCB];
#pragma unroll
        for (int l = 0; l < FCB; l++) acc[l] = bias;
        const float* wr = fcw + tid * FC_LEN;
        for (int i = 0; i < FC_LEN; i += 4) {
            float4 w4 = *reinterpret_cast<const float4*>(wr + i);
#pragma unroll
            for (int l = 0; l < FCB; l++) {
                float4 f4 = *reinterpret_cast<const float4*>(&fs[l * FC_LEN + i]);
                acc[l] += f4.x * w4.x + f4.y * w4.y + f4.z * w4.z + f4.w * w4.w;
            }
        }
        float s = 0.f, ss = 0.f;
#pragma unroll
        for (int l = 0; l < FCB; l++) {
            g_y[(b0 + l) * DT + tid] = acc[l];
            s += acc[l];
            ss += acc[l] * acc[l];
        }
        atomicAdd(&g_bn2sum[tid], s);
        atomicAdd(&g_bn2ss[tid], ss);
    }
}

__global__ void k_bn2fin(const float* __restrict__ g, const float* __restrict__ b) {
    int k = threadIdx.x;
    if (k >= DT) return;
    float cnt = (float)BATCH;
    float mean = g_bn2sum[k] / cnt;
    float var = g_bn2ss[k] / cnt - mean * mean;
    float inv = rsqrtf(var + EPS);
    float sc = g[k] * inv;
    g_bn2sc[k] = sc;
    g_bn2sh[k] = b[k] - sc * mean;
}

// z = relu(bn2(y)), zero-padded to DTP columns
__global__ void k_bn2apply() {
    int i = blockIdx.x * blockDim.x + threadIdx.x;
    if (i >= BATCH * DTP) return;
    int k = i % DTP;
    float v = 0.f;
    if (k < DT) v = fmaxf(g_bn2sc[k] * g_y[(i / DTP) * DT + k] + g_bn2sh[k], 0.f);
    g_z[i] = v;
}

// final GEMM: out = sigmoid(z @ Tw^T + b). 128x128x16 double-buffered SGEMM.
#define BM 128
#define BN 128
#define BK 16
__global__ void __launch_bounds__(256) k_out(const float* __restrict__ Tw,
                                             const float* __restrict__ bbias,
                                             float* __restrict__ out) {
    __shared__ float As[2][BK][BM];
    __shared__ float Bs[2][BK][BN];
    int t = threadIdx.x;
    int tx = t & 15, ty = t >> 4;
    int m0 = blockIdx.x * BM;
    int n0 = blockIdx.y * BN;
    int lr = t >> 2;         // 0..63
    int lk = (t & 3) * 4;    // 0,4,8,12

    float acc[8][8];
#pragma unroll
    for (int i = 0; i < 8; i++)
#pragma unroll
        for (int j = 0; j < 8; j++) acc[i][j] = 0.f;

    float4 pa[2], pb[2];
    // prologue: tile 0
#pragma unroll
    for (int r = 0; r < 2; r++) {
        int rr = lr + r * 64;
        pa[r] = *reinterpret_cast<const float4*>(&g_z[(m0 + rr) * DTP + lk]);
        float4 bv = make_float4(0.f, 0.f, 0.f, 0.f);
        if (n0 + rr < N_TYPE)
            bv = *reinterpret_cast<const float4*>(&Tw[(n0 + rr) * DT + lk]);
        pb[r] = bv;
    }
#pragma unroll
    for (int r = 0; r < 2; r++) {
        int rr = lr + r * 64;
        As[0][lk + 0][rr] = pa[r].x; As[0][lk + 1][rr] = pa[r].y;
        As[0][lk + 2][rr] = pa[r].z; As[0][lk + 3][rr] = pa[r].w;
        Bs[0][lk + 0][rr] = pb[r].x; Bs[0][lk + 1][rr] = pb[r].y;
        Bs[0][lk + 2][rr] = pb[r].z; Bs[0][lk + 3][rr] = pb[r].w;
    }
    __syncthreads();

    const int NK = DTP / BK;  // 13
    for (int kt = 0; kt < NK; kt++) {
        int cur = kt & 1;
        if (kt + 1 < NK) {
            int kb = (kt + 1) * BK;
#pragma unroll
            for (int r = 0; r < 2; r++) {
                int rr = lr + r * 64;
                pa[r] = *reinterpret_cast<const float4*>(&g_z[(m0 + rr) * DTP + kb + lk]);
                float4 bv = make_float4(0.f, 0.f, 0.f, 0.f);
                if (n0 + rr < N_TYPE && kb + lk < DT)
                    bv = *reinterpret_cast<const float4*>(&Tw[(n0 + rr) * DT + kb + lk]);
                pb[r] = bv;
            }
        }
#pragma unroll
        for (int kk = 0; kk < BK; kk++) {
            float4 a0 = *reinterpret_cast<const float4*>(&As[cur][kk][ty * 8]);
            float4 a1 = *reinterpret_cast<const float4*>(&As[cur][kk][ty * 8 + 4]);
            float4 b0 = *reinterpret_cast<const float4*>(&Bs[cur][kk][tx * 8]);
            float4 b1 = *reinterpret_cast<const float4*>(&Bs[cur][kk][tx * 8 + 4]);
            float av_[8] = {a0.x, a0.y, a0.z, a0.w, a1.x, a1.y, a1.z, a1.w};
            float bv_[8] = {b0.x, b0.y, b0.z, b0.w, b1.x, b1.y, b1.z, b1.w};
#pragma unroll
            for (int i = 0; i < 8; i++)
#pragma unroll
                for (int j = 0; j < 8; j++) acc[i][j] += av_[i] * bv_[j];
        }
        if (kt + 1 < NK) {
            int nxt = cur ^ 1;
#pragma unroll
            for (int r = 0; r < 2; r++) {
                int rr = lr + r * 64;
                As[nxt][lk + 0][rr] = pa[r].x; As[nxt][lk + 1][rr] = pa[r].y;
                As[nxt][lk + 2][rr] = pa[r].z; As[nxt][lk + 3][rr] = pa[r].w;
                Bs[nxt][lk + 0][rr] = pb[r].x; Bs[nxt][lk + 1][rr] = pb[r].y;
                Bs[nxt][lk + 2][rr] = pb[r].z; Bs[nxt][lk + 3][rr] = pb[r].w;
            }
            __syncthreads();
        }
    }

#pragma unroll
    for (int i = 0; i < 8; i++) {
        int m = m0 + ty * 8 + i;
#pragma unroll
        for (int j = 0; j < 8; j++) {
            int n = n0 + tx * 8 + j;
            if (n < N_TYPE) {
                float l = acc[i][j] + bbias[n];
                out[m * N_TYPE + n] = 1.f / (1.f + expf(-l));
            }
        }
    }
}

// ---------------- launch ----------------
extern "C" void kernel_launch(void* const* d_in, const int* in_sizes, int n_in,
                              void* d_out, int out_size) {
    const int* xb = (const int*)d_in[0];
    const int* ei = (const int*)d_in[1];
    const int* et = (const int*)d_in[2];
    const float* Ew = (const float*)d_in[3];
    const float* Rw = (const float*)d_in[4];
    const float* Tw = (const float*)d_in[5];
    const float* Wf = (const float*)d_in[6];
    const float* av = (const float*)d_in[7];
    const float* cw = (const float*)d_in[8];
    const float* cb = (const float*)d_in[9];
    const float* b1g = (const float*)d_in[10];
    const float* b1b = (const float*)d_in[11];
    const float* b3g = (const float*)d_in[12];
    const float* b3b = (const float*)d_in[13];
    const float* b2g = (const float*)d_in[14];
    const float* b2b = (const float*)d_in[15];
    const float* fcw = (const float*)d_in[16];
    const float* fcb = (const float*)d_in[17];
    const float* bbias = (const float*)d_in[18];
    float* out = (float*)d_out;

    k_zero<<<512, 256>>>();
    k_flag<<<BATCH, NOUT>>>(xb);
    k_compact<<<(N_EDGE + 255) / 256, 256>>>(ei, et);
    k_wa<<<1, 128>>>(Wf, av);
    k_hd<<<(N_ENT + 7) / 8, 256>>>(Ew);
    k_h16<<<N_ENT / 16, 128>>>(Ew, Wf);
    k_rproj<<<N_REL, NOUT>>>(Rw, Wf, av);
    k_score<<<512, 256>>>();
    k_agg<<<1024, 256>>>();
    k_gather<<<BATCH, NOUT>>>(xb);
    k_bn1fin<<<1, 1>>>(b1g, b1b);
    k_conv<<<BATCH, 256>>>(cw, cb);
    k_bn3fin<<<1, 32>>>(b3g, b3b);
    k_fc<<<BATCH / FCB, 256>>>(fcw, fcb);
    k_bn2fin<<<1, DT>>>(b2g, b2b);
    k_bn2apply<<<(BATCH * DTP + 255) / 256, 256>>>();
    dim3 gg(BATCH / BM, (N_TYPE + BN - 1) / BN);
    k_out<<<gg, 256>>>(Tw, bbias, out);
}

// round 5
// speedup vs baseline: 1.5714x; 1.3458x over previous
#include <cuda_runtime.h>
#include <math.h>

#define N_ENT 50000
#define N_REL 237
#define N_TYPE 4000
#define DE 100
#define NOUT 128
#define DT 200
#define DTP 224
#define N_EDGE 800000
#define BATCH 4096
#define NUM_FILT 32
#define CONV_W 60
#define POOL_W 30
#define FC_LEN 960
#define EPS 1e-5f

// ---------------- scratch ----------------
__device__ float g_h[N_ENT * NOUT];
__device__ float g_hd[N_ENT];
__device__ float g_hm[N_ENT];
__device__ float g_wa1[DE];
__device__ float g_wa2[DE];
__device__ float g_rproj[N_REL * NOUT];
__device__ float g_ra[N_REL];
__device__ float g_denom[N_ENT];
__device__ int   g_flag[N_ENT];
__device__ int   g_ecnt;
__device__ int   g_cs[N_EDGE];
__device__ int   g_cd[N_EDGE];
__device__ int   g_ct[N_EDGE];
__device__ float g_ex[N_EDGE];
__device__ float g_agg[N_ENT * NOUT];
__device__ float g_e[BATCH * NOUT];
__device__ float g_conv[BATCH * NUM_FILT * CONV_W];
__device__ float g_y[BATCH * DT];
__device__ float g_z[BATCH * DTP];              // relu(bn2), tf32-rounded, K-padded
__device__ float g_twc[N_TYPE * DTP];           // Tw tf32-rounded, K-padded
__device__ float g_fcwc[DT * FC_LEN];           // fc_w tf32-rounded
__device__ float g_bn1[4];
__device__ float g_bn3sum[NUM_FILT], g_bn3ss[NUM_FILT];
__device__ float g_bn3sc[NUM_FILT], g_bn3sh[NUM_FILT];
__device__ float g_bn2sc[DT], g_bn2sh[DT];

// ---------------- helpers ----------------
__device__ __forceinline__ unsigned f2tf(float x) {
    unsigned r;
    asm("cvt.rna.tf32.f32 %0, %1;" : "=r"(r) : "f"(x));
    return r;
}

__device__ __forceinline__ void mma_tf32(float c[4], const unsigned a[4], const unsigned b[2]) {
    asm volatile(
        "mma.sync.aligned.m16n8k8.row.col.f32.tf32.tf32.f32 "
        "{%0,%1,%2,%3}, {%4,%5,%6,%7}, {%8,%9}, {%0,%1,%2,%3};"
        : "+f"(c[0]), "+f"(c[1]), "+f"(c[2]), "+f"(c[3])
        : "r"(a[0]), "r"(a[1]), "r"(a[2]), "r"(a[3]), "r"(b[0]), "r"(b[1]));
}

// ---------------- small kernels ----------------

__global__ void k_zero() {
    int tid = blockIdx.x * blockDim.x + threadIdx.x;
    int stride = gridDim.x * blockDim.x;
    for (int i = tid; i < N_ENT; i += stride) { g_denom[i] = 0.f; g_flag[i] = 0; }
    if (tid == 0) g_ecnt = 0;
    if (tid < 2) g_bn1[tid] = 0.f;
    for (int i = tid; i < NUM_FILT; i += stride) { g_bn3sum[i] = 0.f; g_bn3ss[i] = 0.f; }
}

__global__ void k_flag(const int* __restrict__ xb) {
    int n = xb[blockIdx.x];
    if (threadIdx.x == 0) g_flag[n] = 1;
    g_agg[n * NOUT + threadIdx.x] = 0.f;
}

// compact edges whose dst is flagged (warp-aggregated atomics)
__global__ void k_compact(const int* __restrict__ ei, const int* __restrict__ et) {
    int e = blockIdx.x * blockDim.x + threadIdx.x;
    int lane = threadIdx.x & 31;
    int dst = -1;
    bool pred = false;
    if (e < N_EDGE) {
        dst = ei[N_EDGE + e];
        pred = (g_flag[dst] != 0);
    }
    unsigned mask = __ballot_sync(0xffffffffu, pred);
    if (mask == 0) return;
    int leader = __ffs(mask) - 1;
    int base = 0;
    if (lane == leader) base = atomicAdd(&g_ecnt, __popc(mask));
    base = __shfl_sync(0xffffffffu, base, leader);
    if (pred) {
        int pos = base + __popc(mask & ((1u << lane) - 1u));
        g_cs[pos] = ei[e];
        g_cd[pos] = dst;
        g_ct[pos] = et[e];
    }
}

// wa1 = W_f @ a1, wa2 = W_f @ a2   (warp per k-row)
__global__ void k_wa(const float* __restrict__ Wf, const float* __restrict__ av) {
    int k = blockIdx.x * 8 + (threadIdx.x >> 5);
    int lane = threadIdx.x & 31;
    if (k >= DE) return;
    float s1 = 0.f, s2 = 0.f;
#pragma unroll
    for (int q = 0; q < 4; q++) {
        int j = lane + q * 32;
        float w = Wf[k * NOUT + j];
        s1 += w * av[j];
        s2 += w * av[NOUT + j];
    }
#pragma unroll
    for (int o = 16; o > 0; o >>= 1) {
        s1 += __shfl_xor_sync(0xffffffffu, s1, o);
        s2 += __shfl_xor_sync(0xffffffffu, s2, o);
    }
    if (lane == 0) { g_hd[k] = 0.f; g_wa1[k] = s1; g_wa2[k] = s2; }
}

// h = Ew @ Wf (16 nodes/block) ; fused hd/hm
__global__ void k_h16(const float* __restrict__ Ew, const float* __restrict__ Wf) {
    int n0 = blockIdx.x * 16;
    int t = threadIdx.x;
    int jl = t & 31;
    int ng = t >> 5;
    __shared__ float er[16][DE];
    for (int i = t; i < 16 * DE; i += 128) er[i / DE][i % DE] = Ew[n0 * DE + i];
    __syncthreads();
    float acc[4][4];
#pragma unroll
    for (int a = 0; a < 4; a++)
#pragma unroll
        for (int b = 0; b < 4; b++) acc[a][b] = 0.f;
    for (int k = 0; k < DE; k++) {
        float w0 = Wf[k * NOUT + jl];
        float w1 = Wf[k * NOUT + jl + 32];
        float w2 = Wf[k * NOUT + jl + 64];
        float w3 = Wf[k * NOUT + jl + 96];
#pragma unroll
        for (int nn = 0; nn < 4; nn++) {
            float e = er[ng * 4 + nn][k];
            acc[nn][0] += e * w0;
            acc[nn][1] += e * w1;
            acc[nn][2] += e * w2;
            acc[nn][3] += e * w3;
        }
    }
#pragma unroll
    for (int nn = 0; nn < 4; nn++)
#pragma unroll
        for (int q = 0; q < 4; q++)
            g_h[(n0 + ng * 4 + nn) * NOUT + q * 32 + jl] = acc[nn][q];
    // fused hd/hm: 8 threads per node
    int oct = t >> 3, ol = t & 7;
    float s1 = 0.f, s2 = 0.f;
    for (int k = ol; k < DE; k += 8) {
        float v = er[oct][k];
        s1 += v * g_wa1[k];
        s2 += v * g_wa2[k];
    }
#pragma unroll
    for (int o = 4; o > 0; o >>= 1) {
        s1 += __shfl_xor_sync(0xffffffffu, s1, o);
        s2 += __shfl_xor_sync(0xffffffffu, s2, o);
    }
    if (ol == 0) { g_hd[n0 + oct] = s1; g_hm[n0 + oct] = s2; }
}

// rproj = R_w @ W_f ; ra = rproj . a2
__global__ void k_rproj(const float* __restrict__ Rw, const float* __restrict__ Wf,
                        const float* __restrict__ av) {
    int r = blockIdx.x, j = threadIdx.x;
    __shared__ float rr[DE];
    __shared__ float red[NOUT];
    if (j < DE) rr[j] = Rw[r * DE + j];
    __syncthreads();
    float acc = 0.f;
#pragma unroll 4
    for (int k = 0; k < DE; k++) acc += rr[k] * Wf[k * NOUT + j];
    g_rproj[r * NOUT + j] = acc;
    red[j] = acc * av[NOUT + j];
    __syncthreads();
    for (int s = 64; s > 0; s >>= 1) {
        if (j < s) red[j] += red[j + s];
        __syncthreads();
    }
    if (j == 0) g_ra[r] = red[0];
}

__global__ void k_score() {
    int tid = blockIdx.x * blockDim.x + threadIdx.x;
    int stride = gridDim.x * blockDim.x;
    int cnt = g_ecnt;
    for (int e = tid; e < cnt; e += stride) {
        int src = g_cs[e], dst = g_cd[e], t = g_ct[e];
        float s = g_hd[dst] + g_hm[src] - g_ra[t];
        s = (s >= 0.f) ? s : 0.2f * s;
        float ex = expf(s);
        g_ex[e] = ex;
        atomicAdd(&g_denom[dst], ex);
    }
}

__global__ void k_agg() {
    int w = (blockIdx.x * blockDim.x + threadIdx.x) >> 5;
    int nwarp = (gridDim.x * blockDim.x) >> 5;
    int lane = threadIdx.x & 31;
    int cnt = g_ecnt;
    for (int e = w; e < cnt; e += nwarp) {
        int src = g_cs[e], dst = g_cd[e], t = g_ct[e];
        float wt = g_ex[e] / (g_denom[dst] + 1e-16f);
        float4 a = reinterpret_cast<const float4*>(&g_h[src * NOUT])[lane];
        float4 b = reinterpret_cast<const float4*>(&g_rproj[t * NOUT])[lane];
        float4 v;
        v.x = wt * (a.x - b.x); v.y = wt * (a.y - b.y);
        v.z = wt * (a.z - b.z); v.w = wt * (a.w - b.w);
        float* p = &g_agg[dst * NOUT + lane * 4];
        asm volatile("red.global.add.v4.f32 [%0], {%1,%2,%3,%4};"
                     :: "l"(p), "f"(v.x), "f"(v.y), "f"(v.z), "f"(v.w) : "memory");
    }
}

__global__ void k_gather(const int* __restrict__ xb) {
    int b = blockIdx.x, j = threadIdx.x;
    __shared__ float r1[NOUT], r2[NOUT];
    float v = g_agg[xb[b] * NOUT + j];
    float e = (v > 0.f) ? v : expm1f(v);
    g_e[b * NOUT + j] = e;
    r1[j] = e;
    r2[j] = e * e;
    __syncthreads();
    for (int s = 64; s > 0; s >>= 1) {
        if (j < s) { r1[j] += r1[j + s]; r2[j] += r2[j + s]; }
        __syncthreads();
    }
    if (j == 0) { atomicAdd(&g_bn1[0], r1[0]); atomicAdd(&g_bn1[1], r2[0]); }
}

__global__ void k_bn1fin(const float* __restrict__ g, const float* __restrict__ b) {
    float cnt = (float)(BATCH * NOUT);
    float mean = g_bn1[0] / cnt;
    float var = g_bn1[1] / cnt - mean * mean;
    float inv = rsqrtf(var + EPS);
    float sc = g[0] * inv;
    g_bn1[2] = sc;
    g_bn1[3] = b[0] - sc * mean;
}

__global__ void k_conv(const float* __restrict__ cw, const float* __restrict__ cb) {
    int b = blockIdx.x, tid = threadIdx.x;
    __shared__ float es[NOUT];
    __shared__ float wsm[NUM_FILT * 9];
    __shared__ float co[NUM_FILT * CONV_W];
    float sc = g_bn1[2], sh = g_bn1[3];
    if (tid < NOUT) es[tid] = sc * g_e[b * NOUT + tid] + sh;
    for (int i = tid; i < NUM_FILT * 9; i += blockDim.x) wsm[i] = cw[i];
    __syncthreads();
    for (int i = tid; i < NUM_FILT * CONV_W; i += blockDim.x) {
        int c = i / CONV_W, w = i % CONV_W;
        float acc = cb[c];
#pragma unroll
        for (int k = 0; k < 9; k++) acc += wsm[c * 9 + k] * es[2 * w + k];
        co[i] = acc;
        g_conv[b * NUM_FILT * CONV_W + i] = acc;
    }
    __syncthreads();
    if (tid < NUM_FILT) {
        float s = 0.f, ss = 0.f;
        for (int w = 0; w < CONV_W; w++) {
            float v = co[tid * CONV_W + w];
            s += v; ss += v * v;
        }
        atomicAdd(&g_bn3sum[tid], s);
        atomicAdd(&g_bn3ss[tid], ss);
    }
}

__global__ void k_bn3fin(const float* __restrict__ g, const float* __restrict__ b) {
    int c = threadIdx.x;
    if (c >= NUM_FILT) return;
    float cnt = (float)(BATCH * CONV_W);
    float mean = g_bn3sum[c] / cnt;
    float var = g_bn3ss[c] / cnt - mean * mean;
    float inv = rsqrtf(var + EPS);
    float sc = g[c] * inv;
    g_bn3sc[c] = sc;
    g_bn3sh[c] = b[c] - sc * mean;
}

// prep: convert weights to tf32-rounded copies (padded K for Tw)
__global__ void k_prep_tw(const float* __restrict__ Tw) {
    int i = blockIdx.x * blockDim.x + threadIdx.x;
    if (i >= N_TYPE * DTP) return;
    int n = i / DTP, k = i % DTP;
    float v = (k < DT) ? Tw[n * DT + k] : 0.f;
    g_twc[i] = __uint_as_float(f2tf(v));
}

__global__ void k_prep_fcw(const float* __restrict__ fcw) {
    int i = blockIdx.x * blockDim.x + threadIdx.x;
    if (i >= DT * FC_LEN) return;
    g_fcwc[i] = __uint_as_float(f2tf(fcw[i]));
}

// ---------------- tf32 GEMM 1: fc  y[4096,200] = F[4096,960] @ fcw^T ----------------
// F built on the fly: bn3 + relu + maxpool over g_conv.
#define SAP 36
__global__ void __launch_bounds__(256) k_fc(const float* __restrict__ fcb) {
    __shared__ unsigned As[128 * SAP];
    __shared__ unsigned Bs[128 * SAP];
    int t = threadIdx.x;
    int warp = t >> 5, lane = t & 31;
    int wm = warp >> 2, wn = warp & 3;      // 2 x 4 warps
    int g = lane >> 2, tg = lane & 3;
    int m0 = blockIdx.x * 128;
    int n0 = blockIdx.y * 128;
    int lrow = t >> 1, lpart = (t & 1) * 16;

    float c[4][4][4];
#pragma unroll
    for (int i = 0; i < 4; i++)
#pragma unroll
        for (int j = 0; j < 4; j++)
#pragma unroll
            for (int q = 0; q < 4; q++) c[i][j][q] = 0.f;

    for (int kc = 0; kc < FC_LEN / 32; kc++) {
        int k0g = kc * 32;
        // stage A: pooled+bn3+relu features, tf32-rounded
        {
            int b = m0 + lrow;
            const float* crow = &g_conv[b * (NUM_FILT * CONV_W)];
#pragma unroll
            for (int q = 0; q < 16; q++) {
                int kk = k0g + lpart + q;
                int ch = kk / POOL_W, w = kk % POOL_W;
                float sc = g_bn3sc[ch], sh = g_bn3sh[ch];
                float x0 = crow[ch * CONV_W + 2 * w];
                float x1 = crow[ch * CONV_W + 2 * w + 1];
                float v = fmaxf(fmaxf(sc * x0 + sh, sc * x1 + sh), 0.f);
                As[lrow * SAP + lpart + q] = f2tf(v);
            }
        }
        // stage B: fcw rows (guard n<200)
        {
            int n = n0 + lrow;
            if (n < DT) {
                const float4* src = reinterpret_cast<const float4*>(&g_fcwc[n * FC_LEN + k0g + lpart]);
#pragma unroll
                for (int q = 0; q < 4; q++) {
                    float4 v = src[q];
                    Bs[lrow * SAP + lpart + q * 4 + 0] = __float_as_uint(v.x);
                    Bs[lrow * SAP + lpart + q * 4 + 1] = __float_as_uint(v.y);
                    Bs[lrow * SAP + lpart + q * 4 + 2] = __float_as_uint(v.z);
                    Bs[lrow * SAP + lpart + q * 4 + 3] = __float_as_uint(v.w);
                }
            } else {
#pragma unroll
                for (int q = 0; q < 16; q++) Bs[lrow * SAP + lpart + q] = 0u;
            }
        }
        __syncthreads();
#pragma unroll
        for (int kk = 0; kk < 4; kk++) {
            int k0 = kk * 8;
            unsigned ar[4][4], br[4][2];
#pragma unroll
            for (int mt = 0; mt < 4; mt++) {
                int r = wm * 64 + mt * 16 + g;
                ar[mt][0] = As[r * SAP + k0 + tg];
                ar[mt][1] = As[(r + 8) * SAP + k0 + tg];
                ar[mt][2] = As[r * SAP + k0 + tg + 4];
                ar[mt][3] = As[(r + 8) * SAP + k0 + tg + 4];
            }
#pragma unroll
            for (int nt = 0; nt < 4; nt++) {
                int r = wn * 32 + nt * 8 + g;
                br[nt][0] = Bs[r * SAP + k0 + tg];
                br[nt][1] = Bs[r * SAP + k0 + tg + 4];
            }
#pragma unroll
            for (int mt = 0; mt < 4; mt++)
#pragma unroll
                for (int nt = 0; nt < 4; nt++) mma_tf32(c[mt][nt], ar[mt], br[nt]);
        }
        __syncthreads();
    }
    // epilogue: y = c + fcb
#pragma unroll
    for (int mt = 0; mt < 4; mt++) {
        int mrow = m0 + wm * 64 + mt * 16 + g;
#pragma unroll
        for (int nt = 0; nt < 4; nt++) {
            int n = n0 + wn * 32 + nt * 8 + 2 * tg;
            if (n < DT)     g_y[mrow * DT + n]           = c[mt][nt][0] + fcb[n];
            if (n + 1 < DT) g_y[mrow * DT + n + 1]       = c[mt][nt][1] + fcb[n + 1];
            if (n < DT)     g_y[(mrow + 8) * DT + n]     = c[mt][nt][2] + fcb[n];
            if (n + 1 < DT) g_y[(mrow + 8) * DT + n + 1] = c[mt][nt][3] + fcb[n + 1];
        }
    }
}

// bn2 stats + finalize: one block per feature column
__global__ void k_bn2(const float* __restrict__ g, const float* __restrict__ b) {
    int k = blockIdx.x, tid = threadIdx.x;
    __shared__ float r1[128], r2[128];
    float s = 0.f, ss = 0.f;
    for (int i = tid; i < BATCH; i += 128) {
        float v = g_y[i * DT + k];
        s += v; ss += v * v;
    }
    r1[tid] = s; r2[tid] = ss;
    __syncthreads();
    for (int o = 64; o > 0; o >>= 1) {
        if (tid < o) { r1[tid] += r1[tid + o]; r2[tid] += r2[tid + o]; }
        __syncthreads();
    }
    if (tid == 0) {
        float cnt = (float)BATCH;
        float mean = r1[0] / cnt;
        float var = r2[0] / cnt - mean * mean;
        float inv = rsqrtf(var + EPS);
        float sc = g[k] * inv;
        g_bn2sc[k] = sc;
        g_bn2sh[k] = b[k] - sc * mean;
    }
}

// z = relu(bn2(y)), tf32-rounded, zero-padded to DTP
__global__ void k_bn2apply() {
    int i = blockIdx.x * blockDim.x + threadIdx.x;
    if (i >= BATCH * DTP) return;
    int k = i % DTP;
    float v = 0.f;
    if (k < DT) v = fmaxf(g_bn2sc[k] * g_y[(i / DTP) * DT + k] + g_bn2sh[k], 0.f);
    g_z[i] = __uint_as_float(f2tf(v));
}

// ---------------- tf32 GEMM 2: out = sigmoid(Z @ Tw^T + bias) ----------------
__global__ void __launch_bounds__(256) k_out(const float* __restrict__ bbias,
                                             float* __restrict__ out) {
    __shared__ unsigned As[128 * SAP];
    __shared__ unsigned Bs[128 * SAP];
    int t = threadIdx.x;
    int warp = t >> 5, lane = t & 31;
    int wm = warp >> 2, wn = warp & 3;
    int g = lane >> 2, tg = lane & 3;
    int m0 = blockIdx.x * 128;
    int n0 = blockIdx.y * 128;
    int lrow = t >> 1, lpart = (t & 1) * 16;

    float c[4][4][4];
#pragma unroll
    for (int i = 0; i < 4; i++)
#pragma unroll
        for (int j = 0; j < 4; j++)
#pragma unroll
            for (int q = 0; q < 4; q++) c[i][j][q] = 0.f;

    for (int kc = 0; kc < DTP / 32; kc++) {
        int k0g = kc * 32;
        {
            const float4* src = reinterpret_cast<const float4*>(&g_z[(m0 + lrow) * DTP + k0g + lpart]);
#pragma unroll
            for (int q = 0; q < 4; q++) {
                float4 v = src[q];
                As[lrow * SAP + lpart + q * 4 + 0] = __float_as_uint(v.x);
                As[lrow * SAP + lpart + q * 4 + 1] = __float_as_uint(v.y);
                As[lrow * SAP + lpart + q * 4 + 2] = __float_as_uint(v.z);
                As[lrow * SAP + lpart + q * 4 + 3] = __float_as_uint(v.w);
            }
        }
        {
            int n = n0 + lrow;
            if (n < N_TYPE) {
                const float4* src = reinterpret_cast<const float4*>(&g_twc[n * DTP + k0g + lpart]);
#pragma unroll
                for (int q = 0; q < 4; q++) {
                    float4 v = src[q];
                    Bs[lrow * SAP + lpart + q * 4 + 0] = __float_as_uint(v.x);
                    Bs[lrow * SAP + lpart + q * 4 + 1] = __float_as_uint(v.y);
                    Bs[lrow * SAP + lpart + q * 4 + 2] = __float_as_uint(v.z);
                    Bs[lrow * SAP + lpart + q * 4 + 3] = __float_as_uint(v.w);
                }
            } else {
#pragma unroll
                for (int q = 0; q < 16; q++) Bs[lrow * SAP + lpart + q] = 0u;
            }
        }
        __syncthreads();
#pragma unroll
        for (int kk = 0; kk < 4; kk++) {
            int k0 = kk * 8;
            unsigned ar[4][4], br[4][2];
#pragma unroll
            for (int mt = 0; mt < 4; mt++) {
                int r = wm * 64 + mt * 16 + g;
                ar[mt][0] = As[r * SAP + k0 + tg];
                ar[mt][1] = As[(r + 8) * SAP + k0 + tg];
                ar[mt][2] = As[r * SAP + k0 + tg + 4];
                ar[mt][3] = As[(r + 8) * SAP + k0 + tg + 4];
            }
#pragma unroll
            for (int nt = 0; nt < 4; nt++) {
                int r = wn * 32 + nt * 8 + g;
                br[nt][0] = Bs[r * SAP + k0 + tg];
                br[nt][1] = Bs[r * SAP + k0 + tg + 4];
            }
#pragma unroll
            for (int mt = 0; mt < 4; mt++)
#pragma unroll
                for (int nt = 0; nt < 4; nt++) mma_tf32(c[mt][nt], ar[mt], br[nt]);
        }
        __syncthreads();
    }
#pragma unroll
    for (int mt = 0; mt < 4; mt++) {
        int mrow = m0 + wm * 64 + mt * 16 + g;
#pragma unroll
        for (int nt = 0; nt < 4; nt++) {
            int n = n0 + wn * 32 + nt * 8 + 2 * tg;
            if (n < N_TYPE) {
                float b0 = bbias[n];
                out[mrow * N_TYPE + n] = 1.f / (1.f + expf(-(c[mt][nt][0] + b0)));
                out[(mrow + 8) * N_TYPE + n] = 1.f / (1.f + expf(-(c[mt][nt][2] + b0)));
            }
            if (n + 1 < N_TYPE) {
                float b1 = bbias[n + 1];
                out[mrow * N_TYPE + n + 1] = 1.f / (1.f + expf(-(c[mt][nt][1] + b1)));
                out[(mrow + 8) * N_TYPE + n + 1] = 1.f / (1.f + expf(-(c[mt][nt][3] + b1)));
            }
        }
    }
}

// ---------------- launch ----------------
extern "C" void kernel_launch(void* const* d_in, const int* in_sizes, int n_in,
                              void* d_out, int out_size) {
    const int* xb = (const int*)d_in[0];
    const int* ei = (const int*)d_in[1];
    const int* et = (const int*)d_in[2];
    const float* Ew = (const float*)d_in[3];
    const float* Rw = (const float*)d_in[4];
    const float* Tw = (const float*)d_in[5];
    const float* Wf = (const float*)d_in[6];
    const float* av = (const float*)d_in[7];
    const float* cw = (const float*)d_in[8];
    const float* cb = (const float*)d_in[9];
    const float* b1g = (const float*)d_in[10];
    const float* b1b = (const float*)d_in[11];
    const float* b3g = (const float*)d_in[12];
    const float* b3b = (const float*)d_in[13];
    const float* b2g = (const float*)d_in[14];
    const float* b2b = (const float*)d_in[15];
    const float* fcw = (const float*)d_in[16];
    const float* fcb = (const float*)d_in[17];
    const float* bbias = (const float*)d_in[18];
    float* out = (float*)d_out;

    k_zero<<<512, 256>>>();
    k_flag<<<BATCH, NOUT>>>(xb);
    k_compact<<<(N_EDGE + 255) / 256, 256>>>(ei, et);
    k_wa<<<13, 256>>>(Wf, av);
    k_h16<<<N_ENT / 16, 128>>>(Ew, Wf);
    k_rproj<<<N_REL, NOUT>>>(Rw, Wf, av);
    k_score<<<512, 256>>>();
    k_agg<<<1024, 256>>>();
    k_gather<<<BATCH, NOUT>>>(xb);
    k_bn1fin<<<1, 1>>>(b1g, b1b);
    k_conv<<<BATCH, 256>>>(cw, cb);
    k_bn3fin<<<1, 32>>>(b3g, b3b);
    k_prep_fcw<<<(DT * FC_LEN + 255) / 256, 256>>>(fcw);
    {
        dim3 gg(BATCH / 128, 2);
        k_fc<<<gg, 256>>>(fcb);
    }
    k_bn2<<<DT, 128>>>(b2g, b2b);
    k_bn2apply<<<(BATCH * DTP + 255) / 256, 256>>>();
    k_prep_tw<<<(N_TYPE * DTP + 255) / 256, 256>>>(Tw);
    {
        dim3 gg(BATCH / 128, (N_TYPE + 127) / 128);
        k_out<<<gg, 256>>>(bbias, out);
    }
}

// round 6
// speedup vs baseline: 1.5773x; 1.0037x over previous
#include <cuda_runtime.h>
#include <math.h>

#define N_ENT 50000
#define N_REL 237
#define N_TYPE 4000
#define DE 100
#define NOUT 128
#define DT 200
#define DTP 224
#define N_EDGE 800000
#define BATCH 4096
#define NUM_FILT 32
#define CONV_W 60
#define POOL_W 30
#define FC_LEN 960
#define EPS 1e-5f

// ---------------- scratch ----------------
__device__ float g_h[N_ENT * NOUT];
__device__ float g_hd[N_ENT];
__device__ float g_hm[N_ENT];
__device__ float g_wa1[DE];
__device__ float g_wa2[DE];
__device__ float g_rproj[N_REL * NOUT];
__device__ float g_ra[N_REL];
__device__ float g_denom[N_ENT];
__device__ int   g_flag[N_ENT];
__device__ int   g_ecnt;
__device__ int   g_cs[N_EDGE];
__device__ int   g_cd[N_EDGE];
__device__ int   g_ct[N_EDGE];
__device__ float g_ex[N_EDGE];
__device__ float g_agg[N_ENT * NOUT];
__device__ float g_e[BATCH * NOUT];
__device__ float g_conv[BATCH * NUM_FILT * CONV_W];
__device__ float g_y[BATCH * DT];
__device__ float g_z[BATCH * DTP];              // relu(bn2), tf32-rounded, K-padded
__device__ float g_twc[N_TYPE * DTP];           // Tw tf32-rounded, K-padded
__device__ float g_fcwc[DT * FC_LEN];           // fc_w tf32-rounded
__device__ float g_bn1[4];
__device__ float g_bn3sum[NUM_FILT], g_bn3ss[NUM_FILT];
__device__ float g_bn3sc[NUM_FILT], g_bn3sh[NUM_FILT];
__device__ float g_bn2sc[DT], g_bn2sh[DT];

// ---------------- helpers ----------------
__device__ __forceinline__ unsigned f2tf(float x) {
    unsigned r;
    asm("cvt.rna.tf32.f32 %0, %1;" : "=r"(r) : "f"(x));
    return r;
}

__device__ __forceinline__ void mma_tf32(float c[4], const unsigned a[4], const unsigned b[2]) {
    asm volatile(
        "mma.sync.aligned.m16n8k8.row.col.f32.tf32.tf32.f32 "
        "{%0,%1,%2,%3}, {%4,%5,%6,%7}, {%8,%9}, {%0,%1,%2,%3};"
        : "+f"(c[0]), "+f"(c[1]), "+f"(c[2]), "+f"(c[3])
        : "r"(a[0]), "r"(a[1]), "r"(a[2]), "r"(a[3]), "r"(b[0]), "r"(b[1]));
}

// ---------------- small kernels ----------------

__global__ void k_zero() {
    int tid = blockIdx.x * blockDim.x + threadIdx.x;
    int stride = gridDim.x * blockDim.x;
    for (int i = tid; i < N_ENT; i += stride) { g_denom[i] = 0.f; g_flag[i] = 0; }
    if (tid == 0) g_ecnt = 0;
    if (tid < 2) g_bn1[tid] = 0.f;
    for (int i = tid; i < NUM_FILT; i += stride) { g_bn3sum[i] = 0.f; g_bn3ss[i] = 0.f; }
}

__global__ void k_flag(const int* __restrict__ xb) {
    int n = xb[blockIdx.x];
    if (threadIdx.x == 0) g_flag[n] = 1;
    g_agg[n * NOUT + threadIdx.x] = 0.f;
}

// compact edges whose dst is flagged (warp-aggregated atomics)
__global__ void k_compact(const int* __restrict__ ei, const int* __restrict__ et) {
    int e = blockIdx.x * blockDim.x + threadIdx.x;
    int lane = threadIdx.x & 31;
    int dst = -1;
    bool pred = false;
    if (e < N_EDGE) {
        dst = ei[N_EDGE + e];
        pred = (g_flag[dst] != 0);
    }
    unsigned mask = __ballot_sync(0xffffffffu, pred);
    if (mask == 0) return;
    int leader = __ffs(mask) - 1;
    int base = 0;
    if (lane == leader) base = atomicAdd(&g_ecnt, __popc(mask));
    base = __shfl_sync(0xffffffffu, base, leader);
    if (pred) {
        int pos = base + __popc(mask & ((1u << lane) - 1u));
        g_cs[pos] = ei[e];
        g_cd[pos] = dst;
        g_ct[pos] = et[e];
    }
}

// wa1 = W_f @ a1, wa2 = W_f @ a2   (warp per k-row)
__global__ void k_wa(const float* __restrict__ Wf, const float* __restrict__ av) {
    int k = blockIdx.x * 8 + (threadIdx.x >> 5);
    int lane = threadIdx.x & 31;
    if (k >= DE) return;
    float s1 = 0.f, s2 = 0.f;
#pragma unroll
    for (int q = 0; q < 4; q++) {
        int j = lane + q * 32;
        float w = Wf[k * NOUT + j];
        s1 += w * av[j];
        s2 += w * av[NOUT + j];
    }
#pragma unroll
    for (int o = 16; o > 0; o >>= 1) {
        s1 += __shfl_xor_sync(0xffffffffu, s1, o);
        s2 += __shfl_xor_sync(0xffffffffu, s2, o);
    }
    if (lane == 0) { g_hd[k] = 0.f; g_wa1[k] = s1; g_wa2[k] = s2; }
}

// h = Ew @ Wf (16 nodes/block) ; fused hd/hm
__global__ void k_h16(const float* __restrict__ Ew, const float* __restrict__ Wf) {
    int n0 = blockIdx.x * 16;
    int t = threadIdx.x;
    int jl = t & 31;
    int ng = t >> 5;
    __shared__ float er[16][DE];
    for (int i = t; i < 16 * DE; i += 128) er[i / DE][i % DE] = Ew[n0 * DE + i];
    __syncthreads();
    float acc[4][4];
#pragma unroll
    for (int a = 0; a < 4; a++)
#pragma unroll
        for (int b = 0; b < 4; b++) acc[a][b] = 0.f;
    for (int k = 0; k < DE; k++) {
        float w0 = Wf[k * NOUT + jl];
        float w1 = Wf[k * NOUT + jl + 32];
        float w2 = Wf[k * NOUT + jl + 64];
        float w3 = Wf[k * NOUT + jl + 96];
#pragma unroll
        for (int nn = 0; nn < 4; nn++) {
            float e = er[ng * 4 + nn][k];
            acc[nn][0] += e * w0;
            acc[nn][1] += e * w1;
            acc[nn][2] += e * w2;
            acc[nn][3] += e * w3;
        }
    }
#pragma unroll
    for (int nn = 0; nn < 4; nn++)
#pragma unroll
        for (int q = 0; q < 4; q++)
            g_h[(n0 + ng * 4 + nn) * NOUT + q * 32 + jl] = acc[nn][q];
    // fused hd/hm: 8 threads per node
    int oct = t >> 3, ol = t & 7;
    float s1 = 0.f, s2 = 0.f;
    for (int k = ol; k < DE; k += 8) {
        float v = er[oct][k];
        s1 += v * g_wa1[k];
        s2 += v * g_wa2[k];
    }
#pragma unroll
    for (int o = 4; o > 0; o >>= 1) {
        s1 += __shfl_xor_sync(0xffffffffu, s1, o);
        s2 += __shfl_xor_sync(0xffffffffu, s2, o);
    }
    if (ol == 0) { g_hd[n0 + oct] = s1; g_hm[n0 + oct] = s2; }
}

// rproj = R_w @ W_f ; ra = rproj . a2
__global__ void k_rproj(const float* __restrict__ Rw, const float* __restrict__ Wf,
                        const float* __restrict__ av) {
    int r = blockIdx.x, j = threadIdx.x;
    __shared__ float rr[DE];
    __shared__ float red[NOUT];
    if (j < DE) rr[j] = Rw[r * DE + j];
    __syncthreads();
    float acc = 0.f;
#pragma unroll 4
    for (int k = 0; k < DE; k++) acc += rr[k] * Wf[k * NOUT + j];
    g_rproj[r * NOUT + j] = acc;
    red[j] = acc * av[NOUT + j];
    __syncthreads();
    for (int s = 64; s > 0; s >>= 1) {
        if (j < s) red[j] += red[j + s];
        __syncthreads();
    }
    if (j == 0) g_ra[r] = red[0];
}

__global__ void k_score() {
    int tid = blockIdx.x * blockDim.x + threadIdx.x;
    int stride = gridDim.x * blockDim.x;
    int cnt = g_ecnt;
    for (int e = tid; e < cnt; e += stride) {
        int src = g_cs[e], dst = g_cd[e], t = g_ct[e];
        float s = g_hd[dst] + g_hm[src] - g_ra[t];
        s = (s >= 0.f) ? s : 0.2f * s;
        float ex = expf(s);
        g_ex[e] = ex;
        atomicAdd(&g_denom[dst], ex);
    }
}

__global__ void k_agg() {
    int w = (blockIdx.x * blockDim.x + threadIdx.x) >> 5;
    int nwarp = (gridDim.x * blockDim.x) >> 5;
    int lane = threadIdx.x & 31;
    int cnt = g_ecnt;
    for (int e = w; e < cnt; e += nwarp) {
        int src = g_cs[e], dst = g_cd[e], t = g_ct[e];
        float wt = g_ex[e] / (g_denom[dst] + 1e-16f);
        float4 a = reinterpret_cast<const float4*>(&g_h[src * NOUT])[lane];
        float4 b = reinterpret_cast<const float4*>(&g_rproj[t * NOUT])[lane];
        float4 v;
        v.x = wt * (a.x - b.x); v.y = wt * (a.y - b.y);
        v.z = wt * (a.z - b.z); v.w = wt * (a.w - b.w);
        float* p = &g_agg[dst * NOUT + lane * 4];
        asm volatile("red.global.add.v4.f32 [%0], {%1,%2,%3,%4};"
                     :: "l"(p), "f"(v.x), "f"(v.y), "f"(v.z), "f"(v.w) : "memory");
    }
}

__global__ void k_gather(const int* __restrict__ xb) {
    int b = blockIdx.x, j = threadIdx.x;
    __shared__ float r1[NOUT], r2[NOUT];
    float v = g_agg[xb[b] * NOUT + j];
    float e = (v > 0.f) ? v : expm1f(v);
    g_e[b * NOUT + j] = e;
    r1[j] = e;
    r2[j] = e * e;
    __syncthreads();
    for (int s = 64; s > 0; s >>= 1) {
        if (j < s) { r1[j] += r1[j + s]; r2[j] += r2[j + s]; }
        __syncthreads();
    }
    if (j == 0) { atomicAdd(&g_bn1[0], r1[0]); atomicAdd(&g_bn1[1], r2[0]); }
}

__global__ void k_bn1fin(const float* __restrict__ g, const float* __restrict__ b) {
    float cnt = (float)(BATCH * NOUT);
    float mean = g_bn1[0] / cnt;
    float var = g_bn1[1] / cnt - mean * mean;
    float inv = rsqrtf(var + EPS);
    float sc = g[0] * inv;
    g_bn1[2] = sc;
    g_bn1[3] = b[0] - sc * mean;
}

__global__ void k_conv(const float* __restrict__ cw, const float* __restrict__ cb) {
    int b = blockIdx.x, tid = threadIdx.x;
    __shared__ float es[NOUT];
    __shared__ float wsm[NUM_FILT * 9];
    __shared__ float co[NUM_FILT * CONV_W];
    float sc = g_bn1[2], sh = g_bn1[3];
    if (tid < NOUT) es[tid] = sc * g_e[b * NOUT + tid] + sh;
    for (int i = tid; i < NUM_FILT * 9; i += blockDim.x) wsm[i] = cw[i];
    __syncthreads();
    for (int i = tid; i < NUM_FILT * CONV_W; i += blockDim.x) {
        int c = i / CONV_W, w = i % CONV_W;
        float acc = cb[c];
#pragma unroll
        for (int k = 0; k < 9; k++) acc += wsm[c * 9 + k] * es[2 * w + k];
        co[i] = acc;
        g_conv[b * NUM_FILT * CONV_W + i] = acc;
    }
    __syncthreads();
    if (tid < NUM_FILT) {
        float s = 0.f, ss = 0.f;
        for (int w = 0; w < CONV_W; w++) {
            float v = co[tid * CONV_W + w];
            s += v; ss += v * v;
        }
        atomicAdd(&g_bn3sum[tid], s);
        atomicAdd(&g_bn3ss[tid], ss);
    }
}

__global__ void k_bn3fin(const float* __restrict__ g, const float* __restrict__ b) {
    int c = threadIdx.x;
    if (c >= NUM_FILT) return;
    float cnt = (float)(BATCH * CONV_W);
    float mean = g_bn3sum[c] / cnt;
    float var = g_bn3ss[c] / cnt - mean * mean;
    float inv = rsqrtf(var + EPS);
    float sc = g[c] * inv;
    g_bn3sc[c] = sc;
    g_bn3sh[c] = b[c] - sc * mean;
}

// prep: convert weights to tf32-rounded copies (padded K for Tw)
__global__ void k_prep_tw(const float* __restrict__ Tw) {
    int i = blockIdx.x * blockDim.x + threadIdx.x;
    if (i >= N_TYPE * DTP) return;
    int n = i / DTP, k = i % DTP;
    float v = (k < DT) ? Tw[n * DT + k] : 0.f;
    g_twc[i] = __uint_as_float(f2tf(v));
}

__global__ void k_prep_fcw(const float* __restrict__ fcw) {
    int i = blockIdx.x * blockDim.x + threadIdx.x;
    if (i >= DT * FC_LEN) return;
    g_fcwc[i] = __uint_as_float(f2tf(fcw[i]));
}

// ---------------- tf32 GEMM 1: fc  y[4096,200] = F[4096,960] @ fcw^T ----------------
// F built on the fly: bn3 + relu + maxpool over g_conv.
#define SAP 36
__global__ void __launch_bounds__(256) k_fc(const float* __restrict__ fcb) {
    __shared__ unsigned As[128 * SAP];
    __shared__ unsigned Bs[128 * SAP];
    int t = threadIdx.x;
    int warp = t >> 5, lane = t & 31;
    int wm = warp >> 2, wn = warp & 3;      // 2 x 4 warps
    int g = lane >> 2, tg = lane & 3;
    int m0 = blockIdx.x * 128;
    int n0 = blockIdx.y * 128;
    int lrow = t >> 1, lpart = (t & 1) * 16;

    float c[4][4][4];
#pragma unroll
    for (int i = 0; i < 4; i++)
#pragma unroll
        for (int j = 0; j < 4; j++)
#pragma unroll
            for (int q = 0; q < 4; q++) c[i][j][q] = 0.f;

    for (int kc = 0; kc < FC_LEN / 32; kc++) {
        int k0g = kc * 32;
        // stage A: pooled+bn3+relu features, tf32-rounded
        {
            int b = m0 + lrow;
            const float* crow = &g_conv[b * (NUM_FILT * CONV_W)];
#pragma unroll
            for (int q = 0; q < 16; q++) {
                int kk = k0g + lpart + q;
                int ch = kk / POOL_W, w = kk % POOL_W;
                float sc = g_bn3sc[ch], sh = g_bn3sh[ch];
                float x0 = crow[ch * CONV_W + 2 * w];
                float x1 = crow[ch * CONV_W + 2 * w + 1];
                float v = fmaxf(fmaxf(sc * x0 + sh, sc * x1 + sh), 0.f);
                As[lrow * SAP + lpart + q] = f2tf(v);
            }
        }
        // stage B: fcw rows (guard n<200)
        {
            int n = n0 + lrow;
            if (n < DT) {
                const float4* src = reinterpret_cast<const float4*>(&g_fcwc[n * FC_LEN + k0g + lpart]);
#pragma unroll
                for (int q = 0; q < 4; q++) {
                    float4 v = src[q];
                    Bs[lrow * SAP + lpart + q * 4 + 0] = __float_as_uint(v.x);
                    Bs[lrow * SAP + lpart + q * 4 + 1] = __float_as_uint(v.y);
                    Bs[lrow * SAP + lpart + q * 4 + 2] = __float_as_uint(v.z);
                    Bs[lrow * SAP + lpart + q * 4 + 3] = __float_as_uint(v.w);
                }
            } else {
#pragma unroll
                for (int q = 0; q < 16; q++) Bs[lrow * SAP + lpart + q] = 0u;
            }
        }
        __syncthreads();
#pragma unroll
        for (int kk = 0; kk < 4; kk++) {
            int k0 = kk * 8;
            unsigned ar[4][4], br[4][2];
#pragma unroll
            for (int mt = 0; mt < 4; mt++) {
                int r = wm * 64 + mt * 16 + g;
                ar[mt][0] = As[r * SAP + k0 + tg];
                ar[mt][1] = As[(r + 8) * SAP + k0 + tg];
                ar[mt][2] = As[r * SAP + k0 + tg + 4];
                ar[mt][3] = As[(r + 8) * SAP + k0 + tg + 4];
            }
#pragma unroll
            for (int nt = 0; nt < 4; nt++) {
                int r = wn * 32 + nt * 8 + g;
                br[nt][0] = Bs[r * SAP + k0 + tg];
                br[nt][1] = Bs[r * SAP + k0 + tg + 4];
            }
#pragma unroll
            for (int mt = 0; mt < 4; mt++)
#pragma unroll
                for (int nt = 0; nt < 4; nt++) mma_tf32(c[mt][nt], ar[mt], br[nt]);
        }
        __syncthreads();
    }
    // epilogue: y = c + fcb
#pragma unroll
    for (int mt = 0; mt < 4; mt++) {
        int mrow = m0 + wm * 64 + mt * 16 + g;
#pragma unroll
        for (int nt = 0; nt < 4; nt++) {
            int n = n0 + wn * 32 + nt * 8 + 2 * tg;
            if (n < DT)     g_y[mrow * DT + n]           = c[mt][nt][0] + fcb[n];
            if (n + 1 < DT) g_y[mrow * DT + n + 1]       = c[mt][nt][1] + fcb[n + 1];
            if (n < DT)     g_y[(mrow + 8) * DT + n]     = c[mt][nt][2] + fcb[n];
            if (n + 1 < DT) g_y[(mrow + 8) * DT + n + 1] = c[mt][nt][3] + fcb[n + 1];
        }
    }
}

// bn2 stats + finalize: one block per feature column
__global__ void k_bn2(const float* __restrict__ g, const float* __restrict__ b) {
    int k = blockIdx.x, tid = threadIdx.x;
    __shared__ float r1[128], r2[128];
    float s = 0.f, ss = 0.f;
    for (int i = tid; i < BATCH; i += 128) {
        float v = g_y[i * DT + k];
        s += v; ss += v * v;
    }
    r1[tid] = s; r2[tid] = ss;
    __syncthreads();
    for (int o = 64; o > 0; o >>= 1) {
        if (tid < o) { r1[tid] += r1[tid + o]; r2[tid] += r2[tid + o]; }
        __syncthreads();
    }
    if (tid == 0) {
        float cnt = (float)BATCH;
        float mean = r1[0] / cnt;
        float var = r2[0] / cnt - mean * mean;
        float inv = rsqrtf(var + EPS);
        float sc = g[k] * inv;
        g_bn2sc[k] = sc;
        g_bn2sh[k] = b[k] - sc * mean;
    }
}

// z = relu(bn2(y)), tf32-rounded, zero-padded to DTP
__global__ void k_bn2apply() {
    int i = blockIdx.x * blockDim.x + threadIdx.x;
    if (i >= BATCH * DTP) return;
    int k = i % DTP;
    float v = 0.f;
    if (k < DT) v = fmaxf(g_bn2sc[k] * g_y[(i / DTP) * DT + k] + g_bn2sh[k], 0.f);
    g_z[i] = __uint_as_float(f2tf(v));
}

// ---------------- tf32 GEMM 2: out = sigmoid(Z @ Tw^T + bias) ----------------
__global__ void __launch_bounds__(256) k_out(const float* __restrict__ bbias,
                                             float* __restrict__ out) {
    __shared__ unsigned As[128 * SAP];
    __shared__ unsigned Bs[128 * SAP];
    int t = threadIdx.x;
    int warp = t >> 5, lane = t & 31;
    int wm = warp >> 2, wn = warp & 3;
    int g = lane >> 2, tg = lane & 3;
    int m0 = blockIdx.x * 128;
    int n0 = blockIdx.y * 128;
    int lrow = t >> 1, lpart = (t & 1) * 16;

    float c[4][4][4];
#pragma unroll
    for (int i = 0; i < 4; i++)
#pragma unroll
        for (int j = 0; j < 4; j++)
#pragma unroll
            for (int q = 0; q < 4; q++) c[i][j][q] = 0.f;

    for (int kc = 0; kc < DTP / 32; kc++) {
        int k0g = kc * 32;
        {
            const float4* src = reinterpret_cast<const float4*>(&g_z[(m0 + lrow) * DTP + k0g + lpart]);
#pragma unroll
            for (int q = 0; q < 4; q++) {
                float4 v = src[q];
                As[lrow * SAP + lpart + q * 4 + 0] = __float_as_uint(v.x);
                As[lrow * SAP + lpart + q * 4 + 1] = __float_as_uint(v.y);
                As[lrow * SAP + lpart + q * 4 + 2] = __float_as_uint(v.z);
                As[lrow * SAP + lpart + q * 4 + 3] = __float_as_uint(v.w);
            }
        }
        {
            int n = n0 + lrow;
            if (n < N_TYPE) {
                const float4* src = reinterpret_cast<const float4*>(&g_twc[n * DTP + k0g + lpart]);
#pragma unroll
                for (int q = 0; q < 4; q++) {
                    float4 v = src[q];
                    Bs[lrow * SAP + lpart + q * 4 + 0] = __float_as_uint(v.x);
                    Bs[lrow * SAP + lpart + q * 4 + 1] = __float_as_uint(v.y);
                    Bs[lrow * SAP + lpart + q * 4 + 2] = __float_as_uint(v.z);
                    Bs[lrow * SAP + lpart + q * 4 + 3] = __float_as_uint(v.w);
                }
            } else {
#pragma unroll
                for (int q = 0; q < 16; q++) Bs[lrow * SAP + lpart + q] = 0u;
            }
        }
        __syncthreads();
#pragma unroll
        for (int kk = 0; kk < 4; kk++) {
            int k0 = kk * 8;
            unsigned ar[4][4], br[4][2];
#pragma unroll
            for (int mt = 0; mt < 4; mt++) {
                int r = wm * 64 + mt * 16 + g;
                ar[mt][0] = As[r * SAP + k0 + tg];
                ar[mt][1] = As[(r + 8) * SAP + k0 + tg];
                ar[mt][2] = As[r * SAP + k0 + tg + 4];
                ar[mt][3] = As[(r + 8) * SAP + k0 + tg + 4];
            }
#pragma unroll
            for (int nt = 0; nt < 4; nt++) {
                int r = wn * 32 + nt * 8 + g;
                br[nt][0] = Bs[r * SAP + k0 + tg];
                br[nt][1] = Bs[r * SAP + k0 + tg + 4];
            }
#pragma unroll
            for (int mt = 0; mt < 4; mt++)
#pragma unroll
                for (int nt = 0; nt < 4; nt++) mma_tf32(c[mt][nt], ar[mt], br[nt]);
        }
        __syncthreads();
    }
#pragma unroll
    for (int mt = 0; mt < 4; mt++) {
        int mrow = m0 + wm * 64 + mt * 16 + g;
#pragma unroll
        for (int nt = 0; nt < 4; nt++) {
            int n = n0 + wn * 32 + nt * 8 + 2 * tg;
            if (n < N_TYPE) {
                float b0 = bbias[n];
                out[mrow * N_TYPE + n] = 1.f / (1.f + expf(-(c[mt][nt][0] + b0)));
                out[(mrow + 8) * N_TYPE + n] = 1.f / (1.f + expf(-(c[mt][nt][2] + b0)));
            }
            if (n + 1 < N_TYPE) {
                float b1 = bbias[n + 1];
                out[mrow * N_TYPE + n + 1] = 1.f / (1.f + expf(-(c[mt][nt][1] + b1)));
                out[(mrow + 8) * N_TYPE + n + 1] = 1.f / (1.f + expf(-(c[mt][nt][3] + b1)));
            }
        }
    }
}

// ---------------- launch ----------------
extern "C" void kernel_launch(void* const* d_in, const int* in_sizes, int n_in,
                              void* d_out, int out_size) {
    const int* xb = (const int*)d_in[0];
    const int* ei = (const int*)d_in[1];
    const int* et = (const int*)d_in[2];
    const float* Ew = (const float*)d_in[3];
    const float* Rw = (const float*)d_in[4];
    const float* Tw = (const float*)d_in[5];
    const float* Wf = (const float*)d_in[6];
    const float* av = (const float*)d_in[7];
    const float* cw = (const float*)d_in[8];
    const float* cb = (const float*)d_in[9];
    const float* b1g = (const float*)d_in[10];
    const float* b1b = (const float*)d_in[11];
    const float* b3g = (const float*)d_in[12];
    const float* b3b = (const float*)d_in[13];
    const float* b2g = (const float*)d_in[14];
    const float* b2b = (const float*)d_in[15];
    const float* fcw = (const float*)d_in[16];
    const float* fcb = (const float*)d_in[17];
    const float* bbias = (const float*)d_in[18];
    float* out = (float*)d_out;

    k_zero<<<512, 256>>>();
    k_flag<<<BATCH, NOUT>>>(xb);
    k_compact<<<(N_EDGE + 255) / 256, 256>>>(ei, et);
    k_wa<<<13, 256>>>(Wf, av);
    k_h16<<<N_ENT / 16, 128>>>(Ew, Wf);
    k_rproj<<<N_REL, NOUT>>>(Rw, Wf, av);
    k_score<<<512, 256>>>();
    k_agg<<<1024, 256>>>();
    k_gather<<<BATCH, NOUT>>>(xb);
    k_bn1fin<<<1, 1>>>(b1g, b1b);
    k_conv<<<BATCH, 256>>>(cw, cb);
    k_bn3fin<<<1, 32>>>(b3g, b3b);
    k_prep_fcw<<<(DT * FC_LEN + 255) / 256, 256>>>(fcw);
    {
        dim3 gg(BATCH / 128, 2);
        k_fc<<<gg, 256>>>(fcb);
    }
    k_bn2<<<DT, 128>>>(b2g, b2b);
    k_bn2apply<<<(BATCH * DTP + 255) / 256, 256>>>();
    k_prep_tw<<<(N_TYPE * DTP + 255) / 256, 256>>>(Tw);
    {
        dim3 gg(BATCH / 128, (N_TYPE + 127) / 128);
        k_out<<<gg, 256>>>(bbias, out);
    }
}